// round 16
// baseline (speedup 1.0000x reference)
#include <cuda_runtime.h>
#include <cuda_fp16.h>
#include <stdint.h>

#define NSEQ 512
#define SCALE_F 0.04419417382415922f

// ---------------------------------------------------------------------------
// Scratch (device globals: allocation-free rule)
// ---------------------------------------------------------------------------
__device__ __align__(128) __half d_qkv  [16L * 512 * 1024];       // [b][n][1024]: q|k
__device__ __align__(128) __half d_vT   [16L * 16 * 64 * 512];    // [b][l][d][n]
__device__ __align__(128) __half d_xh   [8192L * 512];            // x in fp16
__device__ __align__(128) __half d_sc   [16L * 8  * 512 * 512];   // [b][g][n][m]
__device__ __align__(128) __half d_aw   [16L * 16 * 512 * 512];   // [b][l][n][m]
__device__ __align__(128) __half d_o    [16L * 512 * 1024];       // [b][n][l*64+d]
__device__ __align__(128) __half d_wqkvT[2048L * 512];            // [c][k]  K-major
__device__ __align__(128) __half d_woutT[512L * 1024];            // [n][k]  K-major

// MLP weights in constant memory
__constant__ float cW1[128];
__constant__ float cW2[256];
__constant__ float cb1[16];
__constant__ float cb2[16];
__constant__ float csig[8];

// ---------------------------------------------------------------------------
__device__ __forceinline__ void mma16(float* c, const uint32_t* a, const uint32_t* b) {
    asm volatile(
        "mma.sync.aligned.m16n8k16.row.col.f32.f16.f16.f32 "
        "{%0,%1,%2,%3}, {%4,%5,%6,%7}, {%8,%9}, {%0,%1,%2,%3};\n"
        : "+f"(c[0]), "+f"(c[1]), "+f"(c[2]), "+f"(c[3])
        : "r"(a[0]), "r"(a[1]), "r"(a[2]), "r"(a[3]), "r"(b[0]), "r"(b[1]));
}
__device__ __forceinline__ uint32_t h2u(__half2 v) { return *(uint32_t*)&v; }
__device__ __forceinline__ uint32_t f2h2u(float lo, float hi) {
    __half2 h = __floats2half2_rn(lo, hi);
    return *(uint32_t*)&h;
}
__device__ __forceinline__ void cp16(void* s, const void* g) {
    uint32_t sa = (uint32_t)__cvta_generic_to_shared(s);
    asm volatile("cp.async.cg.shared.global [%0], [%1], 16;\n" :: "r"(sa), "l"(g));
}
__device__ __forceinline__ void ldm_x4(uint32_t* r, const void* p) {
    uint32_t a = (uint32_t)__cvta_generic_to_shared(p);
    asm volatile("ldmatrix.sync.aligned.m8n8.x4.shared.b16 {%0,%1,%2,%3}, [%4];\n"
        : "=r"(r[0]), "=r"(r[1]), "=r"(r[2]), "=r"(r[3]) : "r"(a));
}
__device__ __forceinline__ void stm_x4t(uint32_t addr, uint32_t r0, uint32_t r1,
                                        uint32_t r2, uint32_t r3) {
    asm volatile("stmatrix.sync.aligned.m8n8.x4.trans.shared.b16 [%0], {%1,%2,%3,%4};\n"
        :: "r"(addr), "r"(r0), "r"(r1), "r"(r2), "r"(r3) : "memory");
}

// ---------------------------------------------------------------------------
// Uniform fp16 GEMM: C[M,N] = A[M,K] @ B^T  (A row-major, B K-major [N][K])
// cp.async double-buffered, swizzled smem, non-trans ldmatrix both operands.
// Tile 128 x TNT (TNT = 64 or 128), kc=64, 8 warps (4M x 2N).
// EPI: 0 = half C, 1 = float C, 2 = qkv split (q|k -> d_qkv, v -> d_vT + bias)
// ---------------------------------------------------------------------------
template<int EPI, int TNT>
__global__ __launch_bounds__(256, 2) void gemm_f16(
    const __half* __restrict__ A, const __half* __restrict__ B,
    void* __restrict__ Cv, const float* __restrict__ bias,
    int M, int N, int K, int lda, int ldb, int ldc,
    int innerShift, long sAb, long sAj, long sBb, long sBj, long sCb, long sCj)
{
    extern __shared__ __half smx[];
    __half* As = smx;                       // 2 x 128*64
    __half* Bs = smx + 2 * 128 * 64;        // 2 x TNT*64
    constexpr int NH = TNT / 32;            // B ldmatrix groups per warp
    constexpr int NI = TNT / 16;            // 8-col mma tiles per warp

    const int tid = threadIdx.x;
    const int tilesN = N / TNT;
    const int tm = blockIdx.x / tilesN, tn = blockIdx.x % tilesN;
    const int row0 = tm * 128, col0 = tn * TNT;

    const int z = blockIdx.y;
    const int bb = z >> innerShift, jj = z & ((1 << innerShift) - 1);
    const __half* Ab = A + bb * sAb + jj * sAj;
    const __half* Bb = B + bb * sBb + jj * sBj;

    const int lane = tid & 31, wid = tid >> 5;
    const int wm = wid & 3, wn = wid >> 2;
    const int g = lane >> 2, t = lane & 3;

    const int str = tid >> 3;          // staging row (0..31)
    const int sts = tid & 7;           // staging 16B slice (0..7)

    float c[2][NI][4];
    #pragma unroll
    for (int mi = 0; mi < 2; mi++)
        #pragma unroll
        for (int ni = 0; ni < NI; ni++)
            #pragma unroll
            for (int ci = 0; ci < 4; ci++) c[mi][ni][ci] = 0.0f;

    auto issue_tile = [&](int k0, int buf) {
        __half* Ad = As + buf * (128 * 64);
        __half* Bd = Bs + buf * (TNT * 64);
        #pragma unroll
        for (int i = 0; i < 4; i++) {
            int r = str + i * 32;
            cp16(Ad + r * 64 + ((sts ^ (r & 7)) << 3),
                 Ab + (size_t)(row0 + r) * lda + k0 + (sts << 3));
        }
        #pragma unroll
        for (int i = 0; i < TNT / 32; i++) {
            int r = str + i * 32;
            cp16(Bd + r * 64 + ((sts ^ (r & 7)) << 3),
                 Bb + (size_t)(col0 + r) * ldb + k0 + (sts << 3));
        }
        asm volatile("cp.async.commit_group;\n" ::: "memory");
    };

    const int nk = K >> 6;
    issue_tile(0, 0);
    for (int kt = 0; kt < nk; kt++) {
        if (kt + 1 < nk) {
            issue_tile((kt + 1) << 6, (kt + 1) & 1);
            asm volatile("cp.async.wait_group 1;\n" ::: "memory");
        } else {
            asm volatile("cp.async.wait_group 0;\n" ::: "memory");
        }
        __syncthreads();
        const int buf = kt & 1;
        const __half* Ad = As + buf * (128 * 64);
        const __half* Bd = Bs + buf * (TNT * 64);
        #pragma unroll
        for (int ks = 0; ks < 4; ks++) {
            const int s = ks * 2 + (lane >> 4);
            uint32_t af[2][4];
            #pragma unroll
            for (int mi = 0; mi < 2; mi++) {
                int r = wm * 32 + mi * 16 + (lane & 15);
                ldm_x4(af[mi], Ad + r * 64 + ((s ^ (r & 7)) << 3));
            }
            uint32_t bg[NH][4];
            #pragma unroll
            for (int nh = 0; nh < NH; nh++) {
                int r = wn * (TNT / 2) + nh * 16 + (lane & 15);
                ldm_x4(bg[nh], Bd + r * 64 + ((s ^ (r & 7)) << 3));
            }
            #pragma unroll
            for (int mi = 0; mi < 2; mi++)
                #pragma unroll
                for (int nh = 0; nh < NH; nh++) {
                    uint32_t be[2] = { bg[nh][0], bg[nh][2] };
                    uint32_t bo[2] = { bg[nh][1], bg[nh][3] };
                    mma16(c[mi][2 * nh],     af[mi], be);
                    mma16(c[mi][2 * nh + 1], af[mi], bo);
                }
        }
        __syncthreads();
    }

    // ---- epilogue ----
    #pragma unroll
    for (int mi = 0; mi < 2; mi++)
        #pragma unroll
        for (int ni = 0; ni < NI; ni++) {
            int row = row0 + wm * 32 + mi * 16 + g;
            int col = col0 + wn * (TNT / 2) + ni * 8 + 2 * t;
            if (EPI == 2) {
                if (col < 1024) {
                    d_qkv[(size_t)row * 1024 + col] = __float2half(c[mi][ni][0]);
                    d_qkv[(size_t)row * 1024 + col + 1] = __float2half(c[mi][ni][1]);
                    d_qkv[(size_t)(row + 8) * 1024 + col] = __float2half(c[mi][ni][2]);
                    d_qkv[(size_t)(row + 8) * 1024 + col + 1] = __float2half(c[mi][ni][3]);
                } else {
                    int cc = col - 1024;
                    float bv0 = bias[cc], bv1 = bias[cc + 1];
                    int b_ = row >> 9, n_ = row & 511;
                    size_t base = ((size_t)(b_ * 16 + (cc >> 6)) * 64 + (cc & 63)) * 512;
                    d_vT[base + n_]           = __float2half(c[mi][ni][0] + bv0);
                    d_vT[base + 512 + n_]     = __float2half(c[mi][ni][1] + bv1);
                    d_vT[base + n_ + 8]       = __float2half(c[mi][ni][2] + bv0);
                    d_vT[base + 512 + n_ + 8] = __float2half(c[mi][ni][3] + bv1);
                }
            } else if (EPI == 0) {
                __half* Ch = (__half*)Cv + bb * sCb + jj * sCj;
                *(__half2*)(Ch + (size_t)row * ldc + col) =
                    __floats2half2_rn(c[mi][ni][0], c[mi][ni][1]);
                *(__half2*)(Ch + (size_t)(row + 8) * ldc + col) =
                    __floats2half2_rn(c[mi][ni][2], c[mi][ni][3]);
            } else {
                float* Cf = (float*)Cv + bb * sCb + jj * sCj;
                *(float2*)(Cf + (size_t)row * ldc + col) =
                    make_float2(c[mi][ni][0], c[mi][ni][1]);
                *(float2*)(Cf + (size_t)(row + 8) * ldc + col) =
                    make_float2(c[mi][ni][2], c[mi][ni][3]);
            }
        }
}

// ---------------------------------------------------------------------------
// Prepack: x -> fp16; W -> fp16 K-major transposed
// ---------------------------------------------------------------------------
__global__ __launch_bounds__(256) void prepack(
    const float* __restrict__ x,
    const float* __restrict__ Wq, const float* __restrict__ Wk,
    const float* __restrict__ Wv, const float* __restrict__ Wout)
{
    int idx = blockIdx.x * 256 + threadIdx.x;       // 0 .. 4194303
    d_xh[idx] = __float2half(x[idx]);
    if (idx < 2048 * 512) {                          // wqkvT[c][k]
        int cc = idx >> 9, k = idx & 511;
        float v;
        if (cc < 512)       v = Wq[k * 512 + cc];
        else if (cc < 1024) v = Wk[k * 512 + (cc - 512)];
        else                v = Wv[k * 1024 + (cc - 1024)];
        d_wqkvT[idx] = __float2half(v);
    }
    if (idx < 512 * 1024) {                          // woutT[n][k]
        int n = idx >> 10, k = idx & 1023;
        d_woutT[idx] = __float2half(Wout[k * 512 + n]);
    }
}

// ---------------------------------------------------------------------------
// mish(x) = x * (u^2+2u)/(u^2+2u+2), u = e^x
// ---------------------------------------------------------------------------
__device__ __forceinline__ float mish_f(float x) {
    float u = __expf(x);
    float w = fmaf(u, u, 2.0f * u);
    float r = x * w * __frcp_rn(w + 2.0f);
    return (x > 20.0f) ? x : r;
}

// ---------------------------------------------------------------------------
// k_mid_mma: noise + head-mix MLP on tensor cores + prior + softmax(L).
// aw store path: stmatrix.x4.trans -> smem ([l][m] layout) -> LDS.128+STG.128.
// sc/eps prefetched one tile ahead.
// ---------------------------------------------------------------------------
__global__ __launch_bounds__(256) void k_mid_mma(
    const float* __restrict__ prior, const float* __restrict__ eps)
{
    __shared__ __align__(16) __half stile[8][2][256];   // warp, buf, 16x16

    const int lane = threadIdx.x & 31;
    const int wIn  = threadIdx.x >> 5;
    const int g = lane >> 2, t = lane & 3;
    const int warpGlobal = (blockIdx.x << 3) + wIn;

    uint32_t w1f[2], w2f[2][2];
    float b1v[2][2], b2v[2][2];
    #pragma unroll
    for (int c = 0; c < 2; c++) {
        w1f[c]    = f2h2u(cW1[(2*t)  *16 + 8*c + g], cW1[(2*t+1)*16 + 8*c + g]);
        w2f[c][0] = f2h2u(cW2[(2*t)  *16 + 8*c + g], cW2[(2*t+1)*16 + 8*c + g]);
        w2f[c][1] = f2h2u(cW2[(2*t+8)*16 + 8*c + g], cW2[(2*t+9)*16 + 8*c + g]);
        b1v[c][0] = cb1[8*c + 2*t]; b1v[c][1] = cb1[8*c + 2*t + 1];
        b2v[c][0] = cb2[8*c + 2*t]; b2v[c][1] = cb2[8*c + 2*t + 1];
    }
    const float sg0 = csig[2*t], sg1 = csig[2*t+1];
    const __half2 sig2 = __floats2half2_rn(sg0 * sg0, sg1 * sg1);

    // stmatrix per-lane smem target: tile = lane/8, row = lane%8
    const int tile4 = lane >> 3, rrow = lane & 7;
    const int sOff = ((tile4 & 1) * 8 + rrow) * 16 + (tile4 >> 1) * 8;  // halves
    // LDS/STG mapping
    const int lrow = lane >> 1, lhalf = lane & 1;

    auto ld_in = [&](int tl, uint32_t& scg, uint32_t& scg8, float2& eg, float2& eg8) {
        int m0_ = (tl & 31) << 4;
        int n_  = (tl >> 5) & 511;
        int b_  = tl >> 14;
        const unsigned short* scB = (const unsigned short*)d_sc
            + ((size_t)(b_ * 8 + 2 * t) * 512 + n_) * 512 + m0_;
        unsigned sA  = scB[g];
        unsigned sB_ = scB[262144 + g];
        unsigned sC  = scB[g + 8];
        unsigned sD  = scB[262144 + g + 8];
        scg  = sA | (sB_ << 16);
        scg8 = sC | (sD << 16);
        const float* epB = eps + ((size_t)(b_ * 512 + n_) * 512 + m0_) * 8 + 2 * t;
        eg  = *(const float2*)(epB + (size_t)g * 8);
        eg8 = *(const float2*)(epB + (size_t)(g + 8) * 8);
    };

    uint32_t p_scg, p_scg8; float2 p_eg, p_eg8;
    ld_in(warpGlobal * 8, p_scg, p_scg8, p_eg, p_eg8);

    #pragma unroll 1
    for (int it = 0; it < 8; it++) {
        const int tile = warpGlobal * 8 + it;
        const int m0 = (tile & 31) << 4;
        const int n  = (tile >> 5) & 511;
        const int b  = tile >> 14;

        uint32_t sc_g = p_scg, sc_g8 = p_scg8;
        float2 e_g = p_eg, e_g8 = p_eg8;
        if (it < 7) ld_in(tile + 1, p_scg, p_scg8, p_eg, p_eg8);

        __half2 av0 = __hfma2(sig2, __floats2half2_rn(e_g.x,  e_g.y),  *(__half2*)&sc_g);
        __half2 av1 = __hfma2(sig2, __floats2half2_rn(e_g8.x, e_g8.y), *(__half2*)&sc_g8);

        unsigned pm = (((sc_g  & 0x7fff7fffu) == 0u) ? 1u : 0u)
                    | (((sc_g8 & 0x7fff7fffu) == 0u) ? 2u : 0u);
        pm &= __shfl_xor_sync(0xffffffffu, pm, 1);
        pm &= __shfl_xor_sync(0xffffffffu, pm, 2);

        uint32_t afr[4] = { h2u(av0), h2u(av1), 0u, 0u };
        float h[2][4];
        #pragma unroll
        for (int c = 0; c < 2; c++) {
            h[c][0] = b1v[c][0]; h[c][1] = b1v[c][1];
            h[c][2] = b1v[c][0]; h[c][3] = b1v[c][1];
            uint32_t bfr[2] = { w1f[c], 0u };
            mma16(h[c], afr, bfr);
        }
        #pragma unroll
        for (int c = 0; c < 2; c++)
            #pragma unroll
            for (int i = 0; i < 4; i++) h[c][i] = mish_f(h[c][i]);

        uint32_t a2f[4];
        a2f[0] = f2h2u(h[0][0], h[0][1]);
        a2f[1] = f2h2u(h[0][2], h[0][3]);
        a2f[2] = f2h2u(h[1][0], h[1][1]);
        a2f[3] = f2h2u(h[1][2], h[1][3]);
        float o2[2][4];
        #pragma unroll
        for (int c = 0; c < 2; c++) {
            o2[c][0] = b2v[c][0]; o2[c][1] = b2v[c][1];
            o2[c][2] = b2v[c][0]; o2[c][3] = b2v[c][1];
            mma16(o2[c], a2f, w2f[c]);
        }

        const float* prB = prior + ((size_t)(b * 16) * 512 + n) * 512 + m0;
        float lg[2][4];
        #pragma unroll
        for (int c = 0; c < 2; c++) {
            const int l0 = 8 * c + 2 * t;
            lg[c][0] = fmaf(o2[c][0], SCALE_F, __ldg(prB + (size_t) l0      * 262144 + g));
            lg[c][1] = fmaf(o2[c][1], SCALE_F, __ldg(prB + (size_t)(l0 + 1) * 262144 + g));
            lg[c][2] = fmaf(o2[c][2], SCALE_F, __ldg(prB + (size_t) l0      * 262144 + g + 8));
            lg[c][3] = fmaf(o2[c][3], SCALE_F, __ldg(prB + (size_t)(l0 + 1) * 262144 + g + 8));
        }

        float mx0 = fmaxf(fmaxf(lg[0][0], lg[0][1]), fmaxf(lg[1][0], lg[1][1]));
        mx0 = fmaxf(mx0, __shfl_xor_sync(0xffffffffu, mx0, 1));
        mx0 = fmaxf(mx0, __shfl_xor_sync(0xffffffffu, mx0, 2));
        float mx1 = fmaxf(fmaxf(lg[0][2], lg[0][3]), fmaxf(lg[1][2], lg[1][3]));
        mx1 = fmaxf(mx1, __shfl_xor_sync(0xffffffffu, mx1, 1));
        mx1 = fmaxf(mx1, __shfl_xor_sync(0xffffffffu, mx1, 2));

        float ex[2][4];
        #pragma unroll
        for (int c = 0; c < 2; c++) {
            ex[c][0] = __expf(lg[c][0] - mx0);
            ex[c][1] = __expf(lg[c][1] - mx0);
            ex[c][2] = __expf(lg[c][2] - mx1);
            ex[c][3] = __expf(lg[c][3] - mx1);
        }
        float s0 = (ex[0][0] + ex[0][1]) + (ex[1][0] + ex[1][1]);
        s0 += __shfl_xor_sync(0xffffffffu, s0, 1);
        s0 += __shfl_xor_sync(0xffffffffu, s0, 2);
        float s1 = (ex[0][2] + ex[0][3]) + (ex[1][2] + ex[1][3]);
        s1 += __shfl_xor_sync(0xffffffffu, s1, 1);
        s1 += __shfl_xor_sync(0xffffffffu, s1, 2);
        float inv0 = (pm & 1u) ? 0.0f : __frcp_rn(s0);
        float inv1 = (pm & 2u) ? 0.0f : __frcp_rn(s1);

        // ---- store via stmatrix.trans: smem gets [l][m] 16x16 tile ----
        const int bufw = it & 1;
        __half* sw = &stile[wIn][bufw][0];
        __syncwarp();   // protect buffer reuse from (it-2)
        uint32_t r0 = f2h2u(ex[0][0] * inv0, ex[0][1] * inv0);  // l 0-7,  m 0-7
        uint32_t r1 = f2h2u(ex[1][0] * inv0, ex[1][1] * inv0);  // l 8-15, m 0-7
        uint32_t r2 = f2h2u(ex[0][2] * inv1, ex[0][3] * inv1);  // l 0-7,  m 8-15
        uint32_t r3 = f2h2u(ex[1][2] * inv1, ex[1][3] * inv1);  // l 8-15, m 8-15
        stm_x4t((uint32_t)__cvta_generic_to_shared(sw + sOff), r0, r1, r2, r3);
        __syncwarp();
        uint4 v = *(const uint4*)(sw + lrow * 16 + lhalf * 8);
        __half* awB = d_aw + (size_t)(b * 16) * 262144 + (size_t)n * 512 + m0;
        *(uint4*)(awB + (size_t)lrow * 262144 + lhalf * 8) = v;
    }
}

// ---------------------------------------------------------------------------
extern "C" void kernel_launch(void* const* d_in, const int* in_sizes, int n_in,
                              void* d_out, int out_size)
{
    const float* x     = (const float*)d_in[0];
    const float* prior = (const float*)d_in[1];
    const float* eps   = (const float*)d_in[2];
    const float* Wq    = (const float*)d_in[3];
    const float* Wk    = (const float*)d_in[4];
    const float* Wv    = (const float*)d_in[5];
    const float* bv    = (const float*)d_in[6];
    const float* sigma = (const float*)d_in[7];
    const float* Wp1   = (const float*)d_in[8];
    const float* bp1   = (const float*)d_in[9];
    const float* Wp2   = (const float*)d_in[10];
    const float* bp2   = (const float*)d_in[11];
    const float* Wout  = (const float*)d_in[12];
    float* out = (float*)d_out;

    __half *qkv, *vT, *xh, *sc, *aw, *o, *wqkvT, *woutT;
    cudaGetSymbolAddress((void**)&qkv,   d_qkv);
    cudaGetSymbolAddress((void**)&vT,    d_vT);
    cudaGetSymbolAddress((void**)&xh,    d_xh);
    cudaGetSymbolAddress((void**)&sc,    d_sc);
    cudaGetSymbolAddress((void**)&aw,    d_aw);
    cudaGetSymbolAddress((void**)&o,     d_o);
    cudaGetSymbolAddress((void**)&wqkvT, d_wqkvT);
    cudaGetSymbolAddress((void**)&woutT, d_woutT);

    const long S   = 512L * 512L;       // 262144
    const long SQK = 512L * 1024L;      // per-batch q|k stride

    const int SM128 = 2 * (128 * 64 + 128 * 64) * 2;   // 65536 B
    const int SM64  = 2 * (128 * 64 + 64 * 64) * 2;    // 49152 B
    cudaFuncSetAttribute(gemm_f16<2, 128>, cudaFuncAttributeMaxDynamicSharedMemorySize, SM128);
    cudaFuncSetAttribute(gemm_f16<0, 128>, cudaFuncAttributeMaxDynamicSharedMemorySize, SM128);
    cudaFuncSetAttribute(gemm_f16<1, 128>, cudaFuncAttributeMaxDynamicSharedMemorySize, SM128);
    cudaFuncSetAttribute(gemm_f16<0, 64>,  cudaFuncAttributeMaxDynamicSharedMemorySize, SM64);

    cudaMemcpyToSymbolAsync(cW1,  Wp1,   128 * sizeof(float), 0, cudaMemcpyDeviceToDevice);
    cudaMemcpyToSymbolAsync(cW2,  Wp2,   256 * sizeof(float), 0, cudaMemcpyDeviceToDevice);
    cudaMemcpyToSymbolAsync(cb1,  bp1,    16 * sizeof(float), 0, cudaMemcpyDeviceToDevice);
    cudaMemcpyToSymbolAsync(cb2,  bp2,    16 * sizeof(float), 0, cudaMemcpyDeviceToDevice);
    cudaMemcpyToSymbolAsync(csig, sigma,   8 * sizeof(float), 0, cudaMemcpyDeviceToDevice);

    // 0. prepack (x->fp16, weights transposed fp16)
    prepack<<<16384, 256>>>(x, Wq, Wk, Wv, Wout);

    // 1. qkv: M=8192 N=2048 K=512; q|k -> d_qkv, v -> d_vT (+bias)
    gemm_f16<2, 128><<<dim3(64 * 16, 1), 256, SM128>>>(
        xh, wqkvT, nullptr, bv,
        8192, 2048, 512, 512, 512, 0, 0, 0, 0, 0, 0, 0, 0);

    // 2. scores[b,g] = q_g @ k_g^T   (batch 128)  M=512 N=512 K=64
    gemm_f16<0, 128><<<dim3(4 * 4, 128), 256, SM128>>>(
        qkv, qkv + 512, sc, nullptr,
        512, 512, 64, 1024, 1024, 512,
        3, SQK, 64, SQK, 64, 8 * S, S);

    // 3. noise + MLP + prior + softmax(L)
    k_mid_mma<<<4096, 256>>>(prior, eps);

    // 4. o[b,:,l,:] = aw[b,l] @ vT[b,l]^T   (batch 256)  M=512 N=64 K=512
    gemm_f16<0, 64><<<dim3(4, 256), 256, SM64>>>(
        aw, vT, o, nullptr,
        512, 64, 512, 512, 512, 1024,
        4, 16 * S, S, 16L * 32768, 32768, 512L * 1024, 64);

    // 5. out = o @ Wout   M=8192 N=512 K=1024
    gemm_f16<1, 128><<<dim3(64 * 4, 1), 256, SM128>>>(
        o, woutT, out, nullptr,
        8192, 512, 1024, 1024, 1024, 512,
        0, 0, 0, 0, 0, 0, 0);
}